// round 2
// baseline (speedup 1.0000x reference)
#include <cuda_runtime.h>

#define N_NODES 100000
#define N_EDGES 1600000
#define NB      1024
#define IN_F    32
#define H_F     64

// ---------------- scratch (device globals; no allocations allowed) ----------
__device__ __align__(256) float g_agg1[N_NODES * IN_F];   // 12.8 MB
__device__ __align__(256) float g_h1  [N_NODES * H_F];    // 25.6 MB
__device__ __align__(256) float g_agg2[N_NODES * H_F];    // 25.6 MB
__device__ __align__(256) float g_sum1[NB * H_F];
__device__ __align__(256) float g_sum2[NB * H_F];
__device__ __align__(256) float g_cnt [NB];

// vectorized fp32 global reduction (sm_90+, PTX ISA 8.1 vector red)
__device__ __forceinline__ void red_add_v4(float* addr, float4 v) {
    asm volatile("red.global.add.v4.f32 [%0], {%1, %2, %3, %4};"
                 :: "l"(addr), "f"(v.x), "f"(v.y), "f"(v.z), "f"(v.w)
                 : "memory");
}

// ---------------- init: agg1 = in_feat, zero pools ---------------------------
__global__ void init_kernel(const float* __restrict__ in_feat) {
    int gid = blockIdx.x * blockDim.x + threadIdx.x;
    float4 z = make_float4(0.f, 0.f, 0.f, 0.f);
    if (gid < N_NODES * IN_F / 4)
        reinterpret_cast<float4*>(g_agg1)[gid] =
            __ldg(reinterpret_cast<const float4*>(in_feat) + gid);
    if (gid < NB * H_F / 4) {
        reinterpret_cast<float4*>(g_sum1)[gid] = z;
        reinterpret_cast<float4*>(g_sum2)[gid] = z;
    }
    if (gid < NB / 4)
        reinterpret_cast<float4*>(g_cnt)[gid] = z;
}

// ---------------- edge scatter, layer 1 (32 feats, 2 chunks/thread) ---------
__global__ void edge1_kernel(const int* __restrict__ src,
                             const int* __restrict__ dst,
                             const float* __restrict__ feat) {
    int e = blockIdx.x * blockDim.x + threadIdx.x;
    if (e >= N_EDGES) return;
    int c = blockIdx.y * 2;                // chunk pair: 0,2,4,6
    int s = __ldg(src + e), d = __ldg(dst + e);
    const float* srow = feat + (size_t)s * IN_F;
    float*       drow = g_agg1 + (size_t)d * IN_F;
    float4 v0 = __ldg(reinterpret_cast<const float4*>(srow) + c);
    float4 v1 = __ldg(reinterpret_cast<const float4*>(srow) + c + 1);
    red_add_v4(drow + c * 4,     v0);
    red_add_v4(drow + c * 4 + 4, v1);
}

// ---------------- edge scatter, layer 2 (64 feats, 2 chunks/thread) ---------
__global__ void edge2_kernel(const int* __restrict__ src,
                             const int* __restrict__ dst) {
    int e = blockIdx.x * blockDim.x + threadIdx.x;
    if (e >= N_EDGES) return;
    int c = blockIdx.y * 2;                // chunk pair: 0,2,...,14
    int s = __ldg(src + e), d = __ldg(dst + e);
    const float* srow = g_h1 + (size_t)s * H_F;
    float*       drow = g_agg2 + (size_t)d * H_F;
    float4 v0 = __ldg(reinterpret_cast<const float4*>(srow) + c);
    float4 v1 = __ldg(reinterpret_cast<const float4*>(srow) + c + 1);
    red_add_v4(drow + c * 4,     v0);
    red_add_v4(drow + c * 4 + 4, v1);
}

// ---------------- node MLP 1: x(32) -> relu(64) -> relu(64) -----------------
// fused: writes h1, initializes agg2 = h1, accumulates pooled sum1 + counts
__global__ __launch_bounds__(128)
void mlp1_kernel(const float* __restrict__ w1, const float* __restrict__ b1,
                 const float* __restrict__ w2, const float* __restrict__ b2,
                 const int* __restrict__ gids) {
    __shared__ float wbuf[H_F * H_F];      // reused: w1 then w2
    __shared__ float xs[128 * 33];         // pad-33 rows -> conflict-free
    int tid   = threadIdx.x;
    int nbase = blockIdx.x * 128;

    for (int i = tid; i < IN_F * H_F; i += 128) wbuf[i] = w1[i];
    for (int i = tid; i < 128 * IN_F; i += 128) {
        int node = nbase + i / IN_F;
        float v = (node < N_NODES) ? g_agg1[(size_t)node * IN_F + (i % IN_F)] : 0.f;
        xs[(i / IN_F) * 33 + (i % IN_F)] = v;
    }
    __syncthreads();

    float x[IN_F];
    const float* xrow = xs + tid * 33;
#pragma unroll
    for (int i = 0; i < IN_F; i++) x[i] = xrow[i];

    float t[H_F];
#pragma unroll 4
    for (int j = 0; j < H_F; j++) {
        float s = b1[j];
#pragma unroll
        for (int i = 0; i < IN_F; i++) s += x[i] * wbuf[i * H_F + j];
        t[j] = fmaxf(s, 0.f);
    }
    __syncthreads();
    for (int i = tid; i < H_F * H_F; i += 128) wbuf[i] = w2[i];
    __syncthreads();

    int node = nbase + tid;
    if (node < N_NODES) {
        int g = gids[node];
        float* hrow = g_h1   + (size_t)node * H_F;
        float* arow = g_agg2 + (size_t)node * H_F;
        float* srow = g_sum1 + (size_t)g * H_F;
#pragma unroll 4
        for (int j = 0; j < H_F; j += 4) {
            float4 o;
            float* op = reinterpret_cast<float*>(&o);
#pragma unroll
            for (int q = 0; q < 4; q++) {
                float s = b2[j + q];
#pragma unroll
                for (int i = 0; i < H_F; i++) s += t[i] * wbuf[i * H_F + j + q];
                op[q] = fmaxf(s, 0.f);        // outer relu on h
            }
            *reinterpret_cast<float4*>(hrow + j) = o;
            *reinterpret_cast<float4*>(arow + j) = o;
            red_add_v4(srow + j, o);
        }
        atomicAdd(&g_cnt[g], 1.0f);
    }
}

// ---------------- node MLP 2: x(64) -> relu(64) -> relu(64), pool only ------
__global__ __launch_bounds__(64)
void mlp2_kernel(const float* __restrict__ w1, const float* __restrict__ b1,
                 const float* __restrict__ w2, const float* __restrict__ b2,
                 const int* __restrict__ gids) {
    __shared__ float wbuf[H_F * H_F];
    __shared__ float xs[64 * 65];          // pad-65 rows -> conflict-free
    int tid   = threadIdx.x;
    int nbase = blockIdx.x * 64;

    for (int i = tid; i < H_F * H_F; i += 64) wbuf[i] = w1[i];
    for (int i = tid; i < 64 * H_F; i += 64) {
        int node = nbase + i / H_F;
        float v = (node < N_NODES) ? g_agg2[(size_t)node * H_F + (i % H_F)] : 0.f;
        xs[(i / H_F) * 65 + (i % H_F)] = v;
    }
    __syncthreads();

    float t[H_F];
    const float* xrow = xs + tid * 65;
#pragma unroll 2
    for (int j = 0; j < H_F; j++) {
        float s = b1[j];
#pragma unroll
        for (int i = 0; i < H_F; i++) s += xrow[i] * wbuf[i * H_F + j];
        t[j] = fmaxf(s, 0.f);
    }
    __syncthreads();
    for (int i = tid; i < H_F * H_F; i += 64) wbuf[i] = w2[i];
    __syncthreads();

    int node = nbase + tid;
    if (node < N_NODES) {
        int g = gids[node];
        float* srow = g_sum2 + (size_t)g * H_F;
#pragma unroll 2
        for (int j = 0; j < H_F; j += 4) {
            float4 o;
            float* op = reinterpret_cast<float*>(&o);
#pragma unroll
            for (int q = 0; q < 4; q++) {
                float s = b2[j + q];
#pragma unroll
                for (int i = 0; i < H_F; i++) s += t[i] * wbuf[i * H_F + j + q];
                op[q] = fmaxf(s, 0.f);
            }
            red_add_v4(srow + j, o);
        }
    }
}

// ---------------- final tower: block per graph ------------------------------
__device__ __forceinline__ void lin_layer(const float* __restrict__ x,
                                          float* __restrict__ y,
                                          const float* __restrict__ w,
                                          const float* __restrict__ b,
                                          int nin, int nout, bool do_relu, int t) {
    if (t < nout) {
        float s = b[t];
        for (int i = 0; i < nin; i++) s += x[i] * w[i * nout + t];
        y[t] = do_relu ? fmaxf(s, 0.f) : s;
    }
    __syncthreads();
}

__global__ __launch_bounds__(256)
void tower_kernel(const float* __restrict__ ev,
                  const float* __restrict__ l0w, const float* __restrict__ l0b,
                  const float* __restrict__ l1w, const float* __restrict__ l1b,
                  const float* __restrict__ l2w, const float* __restrict__ l2b,
                  const float* __restrict__ l3w, const float* __restrict__ l3b,
                  const float* __restrict__ l4w, const float* __restrict__ l4b,
                  const float* __restrict__ l5w, const float* __restrict__ l5b,
                  const float* __restrict__ l6w, const float* __restrict__ l6b,
                  float* __restrict__ out) {
    __shared__ float xa[256], xb[256];
    int g = blockIdx.x, t = threadIdx.x;

    if (t < H_F) {
        float c = fmaxf(g_cnt[g], 1.f);
        // hg = rep0 + 2*rep1 = (sum1 + 2*sum2) / cnt
        xa[t] = (g_sum1[g * H_F + t] + 2.f * g_sum2[g * H_F + t]) / c;
    } else if (t < 80) {
        xa[t] = ev[g * 16 + (t - 64)];
    }
    __syncthreads();

    lin_layer(xa, xb, l0w, l0b,  80, 256, true, t);
    lin_layer(xb, xa, l1w, l1b, 256, 128, true, t);
    lin_layer(xa, xb, l2w, l2b, 128, 128, true, t);
    lin_layer(xb, xa, l3w, l3b, 128,  64, true, t);
    lin_layer(xa, xb, l4w, l4b,  64,  64, true, t);
    lin_layer(xb, xa, l5w, l5b,  64,  32, true, t);

    if (t == 0) {
        float s = l6b[0];
#pragma unroll
        for (int i = 0; i < 32; i++) s += xa[i] * l6w[i];
        out[g] = s;
    }
}

// ---------------- launch -----------------------------------------------------
extern "C" void kernel_launch(void* const* d_in, const int* in_sizes, int n_in,
                              void* d_out, int out_size) {
    const float* in_feat = (const float*)d_in[0];
    const float* ev      = (const float*)d_in[1];
    const int*   src     = (const int*)  d_in[2];
    const int*   dst     = (const int*)  d_in[3];
    const int*   gids    = (const int*)  d_in[4];
    const float* c0w1 = (const float*)d_in[5];
    const float* c0b1 = (const float*)d_in[6];
    const float* c0w2 = (const float*)d_in[7];
    const float* c0b2 = (const float*)d_in[8];
    const float* c1w1 = (const float*)d_in[9];
    const float* c1b1 = (const float*)d_in[10];
    const float* c1w2 = (const float*)d_in[11];
    const float* c1b2 = (const float*)d_in[12];
    const float* l0w = (const float*)d_in[13]; const float* l0b = (const float*)d_in[14];
    const float* l1w = (const float*)d_in[15]; const float* l1b = (const float*)d_in[16];
    const float* l2w = (const float*)d_in[17]; const float* l2b = (const float*)d_in[18];
    const float* l3w = (const float*)d_in[19]; const float* l3b = (const float*)d_in[20];
    const float* l4w = (const float*)d_in[21]; const float* l4b = (const float*)d_in[22];
    const float* l5w = (const float*)d_in[23]; const float* l5b = (const float*)d_in[24];
    const float* l6w = (const float*)d_in[25]; const float* l6b = (const float*)d_in[26];
    float* out = (float*)d_out;

    init_kernel<<<(N_NODES * IN_F / 4 + 255) / 256, 256>>>(in_feat);

    dim3 e1g((N_EDGES + 255) / 256, IN_F / 8);   // 4 chunk-pairs
    edge1_kernel<<<e1g, 256>>>(src, dst, in_feat);

    mlp1_kernel<<<(N_NODES + 127) / 128, 128>>>(c0w1, c0b1, c0w2, c0b2, gids);

    dim3 e2g((N_EDGES + 255) / 256, H_F / 8);    // 8 chunk-pairs
    edge2_kernel<<<e2g, 256>>>(src, dst);

    mlp2_kernel<<<(N_NODES + 63) / 64, 64>>>(c1w1, c1b1, c1w2, c1b2, gids);

    tower_kernel<<<NB, 256>>>(ev,
                              l0w, l0b, l1w, l1b, l2w, l2b, l3w, l3b,
                              l4w, l4b, l5w, l5b, l6w, l6b, out);
}

// round 3
// speedup vs baseline: 1.4750x; 1.4750x over previous
#include <cuda_runtime.h>

#define N_NODES 100000
#define N_EDGES 1600000
#define NB      1024
#define IN_F    32
#define H_F     64

// ---------------- scratch (device globals; no allocations allowed) ----------
__device__ __align__(256) float g_agg1[N_NODES * IN_F];   // 12.8 MB
__device__ __align__(256) float g_h1  [N_NODES * H_F];    // 25.6 MB
__device__ __align__(256) float g_agg2[N_NODES * H_F];    // 25.6 MB
__device__ __align__(256) float g_sum1[NB * H_F];
__device__ __align__(256) float g_sum2[NB * H_F];
__device__ __align__(256) float g_cnt [NB];

// vectorized fp32 global reduction (sm_90+)
__device__ __forceinline__ void red_add_v4(float* addr, float4 v) {
    asm volatile("red.global.add.v4.f32 [%0], {%1, %2, %3, %4};"
                 :: "l"(addr), "f"(v.x), "f"(v.y), "f"(v.z), "f"(v.w)
                 : "memory");
}

// ---------------- init: agg1 = in_feat, zero pools ---------------------------
__global__ void init_kernel(const float* __restrict__ in_feat) {
    int gid = blockIdx.x * blockDim.x + threadIdx.x;
    float4 z = make_float4(0.f, 0.f, 0.f, 0.f);
    if (gid < N_NODES * IN_F / 4)
        reinterpret_cast<float4*>(g_agg1)[gid] =
            __ldg(reinterpret_cast<const float4*>(in_feat) + gid);
    if (gid < NB * H_F / 4) {
        reinterpret_cast<float4*>(g_sum1)[gid] = z;
        reinterpret_cast<float4*>(g_sum2)[gid] = z;
    }
    if (gid < NB / 4)
        reinterpret_cast<float4*>(g_cnt)[gid] = z;
}

// ---------------- edge scatter, layer 1: 8 lanes per edge -------------------
// A node row is 32 floats = 128 B = exactly one L1 line. 8 consecutive lanes
// cover one edge's full row -> coalesced gather (1 line) + coalesced scatter.
__global__ __launch_bounds__(256)
void edge1_kernel(const int* __restrict__ src,
                  const int* __restrict__ dst,
                  const float* __restrict__ feat) {
    int t = blockIdx.x * 256 + threadIdx.x;
    int e = t >> 3;
    if (e >= N_EDGES) return;
    int c = t & 7;                          // float4 chunk 0..7
    int s = __ldg(src + e), d = __ldg(dst + e);
    float4 v = __ldg(reinterpret_cast<const float4*>(feat + (size_t)s * IN_F) + c);
    red_add_v4(g_agg1 + (size_t)d * IN_F + c * 4, v);
}

// ---------------- edge scatter, layer 2: 16 lanes per edge ------------------
// Row = 64 floats = 256 B = two L1 lines per edge (vs 16 scattered before).
__global__ __launch_bounds__(256)
void edge2_kernel(const int* __restrict__ src,
                  const int* __restrict__ dst) {
    int t = blockIdx.x * 256 + threadIdx.x;
    int e = t >> 4;
    if (e >= N_EDGES) return;
    int c = t & 15;                         // float4 chunk 0..15
    int s = __ldg(src + e), d = __ldg(dst + e);
    float4 v = __ldg(reinterpret_cast<const float4*>(g_h1 + (size_t)s * H_F) + c);
    red_add_v4(g_agg2 + (size_t)d * H_F + c * 4, v);
}

// ---------------- node MLP 1: x(32) -> relu(64) -> relu(64) -----------------
// fused: writes h1, initializes agg2 = h1, accumulates pooled sum1 + counts
__global__ __launch_bounds__(128)
void mlp1_kernel(const float* __restrict__ w1, const float* __restrict__ b1,
                 const float* __restrict__ w2, const float* __restrict__ b2,
                 const int* __restrict__ gids) {
    __shared__ float wbuf[H_F * H_F];      // reused: w1 then w2
    __shared__ float xs[128 * 33];         // pad-33 rows -> conflict-free
    int tid   = threadIdx.x;
    int nbase = blockIdx.x * 128;

    for (int i = tid; i < IN_F * H_F; i += 128) wbuf[i] = w1[i];
    for (int i = tid; i < 128 * IN_F; i += 128) {
        int node = nbase + i / IN_F;
        float v = (node < N_NODES) ? g_agg1[(size_t)node * IN_F + (i % IN_F)] : 0.f;
        xs[(i / IN_F) * 33 + (i % IN_F)] = v;
    }
    __syncthreads();

    float x[IN_F];
    const float* xrow = xs + tid * 33;
#pragma unroll
    for (int i = 0; i < IN_F; i++) x[i] = xrow[i];

    float t[H_F];
#pragma unroll 4
    for (int j = 0; j < H_F; j++) {
        float s = b1[j];
#pragma unroll
        for (int i = 0; i < IN_F; i++) s += x[i] * wbuf[i * H_F + j];
        t[j] = fmaxf(s, 0.f);
    }
    __syncthreads();
    for (int i = tid; i < H_F * H_F; i += 128) wbuf[i] = w2[i];
    __syncthreads();

    int node = nbase + tid;
    if (node < N_NODES) {
        int g = gids[node];
        float* hrow = g_h1   + (size_t)node * H_F;
        float* arow = g_agg2 + (size_t)node * H_F;
        float* srow = g_sum1 + (size_t)g * H_F;
#pragma unroll 4
        for (int j = 0; j < H_F; j += 4) {
            float4 o;
            float* op = reinterpret_cast<float*>(&o);
#pragma unroll
            for (int q = 0; q < 4; q++) {
                float s = b2[j + q];
#pragma unroll
                for (int i = 0; i < H_F; i++) s += t[i] * wbuf[i * H_F + j + q];
                op[q] = fmaxf(s, 0.f);        // outer relu on h
            }
            *reinterpret_cast<float4*>(hrow + j) = o;
            *reinterpret_cast<float4*>(arow + j) = o;
            red_add_v4(srow + j, o);
        }
        atomicAdd(&g_cnt[g], 1.0f);
    }
}

// ---------------- node MLP 2: x(64) -> relu(64) -> relu(64), pool only ------
__global__ __launch_bounds__(64)
void mlp2_kernel(const float* __restrict__ w1, const float* __restrict__ b1,
                 const float* __restrict__ w2, const float* __restrict__ b2,
                 const int* __restrict__ gids) {
    __shared__ float wbuf[H_F * H_F];
    __shared__ float xs[64 * 65];          // pad-65 rows -> conflict-free
    int tid   = threadIdx.x;
    int nbase = blockIdx.x * 64;

    for (int i = tid; i < H_F * H_F; i += 64) wbuf[i] = w1[i];
    for (int i = tid; i < 64 * H_F; i += 64) {
        int node = nbase + i / H_F;
        float v = (node < N_NODES) ? g_agg2[(size_t)node * H_F + (i % H_F)] : 0.f;
        xs[(i / H_F) * 65 + (i % H_F)] = v;
    }
    __syncthreads();

    float t[H_F];
    const float* xrow = xs + tid * 65;
#pragma unroll 2
    for (int j = 0; j < H_F; j++) {
        float s = b1[j];
#pragma unroll
        for (int i = 0; i < H_F; i++) s += xrow[i] * wbuf[i * H_F + j];
        t[j] = fmaxf(s, 0.f);
    }
    __syncthreads();
    for (int i = tid; i < H_F * H_F; i += 64) wbuf[i] = w2[i];
    __syncthreads();

    int node = nbase + tid;
    if (node < N_NODES) {
        int g = gids[node];
        float* srow = g_sum2 + (size_t)g * H_F;
#pragma unroll 2
        for (int j = 0; j < H_F; j += 4) {
            float4 o;
            float* op = reinterpret_cast<float*>(&o);
#pragma unroll
            for (int q = 0; q < 4; q++) {
                float s = b2[j + q];
#pragma unroll
                for (int i = 0; i < H_F; i++) s += t[i] * wbuf[i * H_F + j + q];
                op[q] = fmaxf(s, 0.f);
            }
            red_add_v4(srow + j, o);
        }
    }
}

// ---------------- final tower: block per graph ------------------------------
__device__ __forceinline__ void lin_layer(const float* __restrict__ x,
                                          float* __restrict__ y,
                                          const float* __restrict__ w,
                                          const float* __restrict__ b,
                                          int nin, int nout, bool do_relu, int t) {
    if (t < nout) {
        float s = b[t];
        for (int i = 0; i < nin; i++) s += x[i] * w[i * nout + t];
        y[t] = do_relu ? fmaxf(s, 0.f) : s;
    }
    __syncthreads();
}

__global__ __launch_bounds__(256)
void tower_kernel(const float* __restrict__ ev,
                  const float* __restrict__ l0w, const float* __restrict__ l0b,
                  const float* __restrict__ l1w, const float* __restrict__ l1b,
                  const float* __restrict__ l2w, const float* __restrict__ l2b,
                  const float* __restrict__ l3w, const float* __restrict__ l3b,
                  const float* __restrict__ l4w, const float* __restrict__ l4b,
                  const float* __restrict__ l5w, const float* __restrict__ l5b,
                  const float* __restrict__ l6w, const float* __restrict__ l6b,
                  float* __restrict__ out) {
    __shared__ float xa[256], xb[256];
    int g = blockIdx.x, t = threadIdx.x;

    if (t < H_F) {
        float c = fmaxf(g_cnt[g], 1.f);
        // hg = rep0 + 2*rep1 = (sum1 + 2*sum2) / cnt
        xa[t] = (g_sum1[g * H_F + t] + 2.f * g_sum2[g * H_F + t]) / c;
    } else if (t < 80) {
        xa[t] = ev[g * 16 + (t - 64)];
    }
    __syncthreads();

    lin_layer(xa, xb, l0w, l0b,  80, 256, true, t);
    lin_layer(xb, xa, l1w, l1b, 256, 128, true, t);
    lin_layer(xa, xb, l2w, l2b, 128, 128, true, t);
    lin_layer(xb, xa, l3w, l3b, 128,  64, true, t);
    lin_layer(xa, xb, l4w, l4b,  64,  64, true, t);
    lin_layer(xb, xa, l5w, l5b,  64,  32, true, t);

    if (t == 0) {
        float s = l6b[0];
#pragma unroll
        for (int i = 0; i < 32; i++) s += xa[i] * l6w[i];
        out[g] = s;
    }
}

// ---------------- launch -----------------------------------------------------
extern "C" void kernel_launch(void* const* d_in, const int* in_sizes, int n_in,
                              void* d_out, int out_size) {
    const float* in_feat = (const float*)d_in[0];
    const float* ev      = (const float*)d_in[1];
    const int*   src     = (const int*)  d_in[2];
    const int*   dst     = (const int*)  d_in[3];
    const int*   gids    = (const int*)  d_in[4];
    const float* c0w1 = (const float*)d_in[5];
    const float* c0b1 = (const float*)d_in[6];
    const float* c0w2 = (const float*)d_in[7];
    const float* c0b2 = (const float*)d_in[8];
    const float* c1w1 = (const float*)d_in[9];
    const float* c1b1 = (const float*)d_in[10];
    const float* c1w2 = (const float*)d_in[11];
    const float* c1b2 = (const float*)d_in[12];
    const float* l0w = (const float*)d_in[13]; const float* l0b = (const float*)d_in[14];
    const float* l1w = (const float*)d_in[15]; const float* l1b = (const float*)d_in[16];
    const float* l2w = (const float*)d_in[17]; const float* l2b = (const float*)d_in[18];
    const float* l3w = (const float*)d_in[19]; const float* l3b = (const float*)d_in[20];
    const float* l4w = (const float*)d_in[21]; const float* l4b = (const float*)d_in[22];
    const float* l5w = (const float*)d_in[23]; const float* l5b = (const float*)d_in[24];
    const float* l6w = (const float*)d_in[25]; const float* l6b = (const float*)d_in[26];
    float* out = (float*)d_out;

    init_kernel<<<(N_NODES * IN_F / 4 + 255) / 256, 256>>>(in_feat);

    // 8 lanes per edge: total threads = N_EDGES * 8
    edge1_kernel<<<(N_EDGES * 8 + 255) / 256, 256>>>(src, dst, in_feat);

    mlp1_kernel<<<(N_NODES + 127) / 128, 128>>>(c0w1, c0b1, c0w2, c0b2, gids);

    // 16 lanes per edge: total threads = N_EDGES * 16
    edge2_kernel<<<(N_EDGES * 16 + 255) / 256, 256>>>(src, dst);

    mlp2_kernel<<<(N_NODES + 63) / 64, 64>>>(c1w1, c1b1, c1w2, c1b2, gids);

    tower_kernel<<<NB, 256>>>(ev,
                              l0w, l0b, l1w, l1b, l2w, l2b, l3w, l3b,
                              l4w, l4b, l5w, l5b, l6w, l6b, out);
}